// round 7
// baseline (speedup 1.0000x reference)
#include <cuda_runtime.h>
#include <cstdint>

#define CIN   256
#define CMID  512
#define COUT  256
#define IMGW  56
#define HW    3136
#define BATCH 32
#define KCONV 2304
#define KT1   72      // KCONV/32

// ---------------- scratch (device globals — allocation-free rule) ----------------
__device__ __align__(16) signed char g_xh[BATCH * CIN * HW];   // x hi-byte plane
__device__ __align__(16) signed char g_xl[BATCH * CIN * HW];   // x lo-byte plane
__device__ __align__(16) float       g_y [BATCH * CMID * HW + 8192];
__device__ __align__(16) uint32_t    g_wA[CMID * KCONV / 4];   // s8 weights, fragment-ordered
__device__ __align__(16) float       g_wB[CMID * COUT];        // 1x1 weights [k][m], tf32

__device__ __forceinline__ uint32_t f2tf32(float f) {
    uint32_t r;
    asm("cvt.rna.tf32.f32 %0, %1;" : "=r"(r) : "f"(f));
    return r;
}
#define CP16(dst, src) \
    asm volatile("cp.async.cg.shared.global [%0], [%1], 16;\n" :: "r"(dst), "l"(src))
#define CP_COMMIT()  asm volatile("cp.async.commit_group;\n")
#define CP_WAIT0()   asm volatile("cp.async.wait_group 0;\n")

// ---------------- prep kernels ----------------
// Fragment-ordered s8 weights: [mb(4)][kt(72)][sub(8)][lane(32)][j(4) u32]
// m = mb*128 + sub*16 + (lane>>2) + (j&1)*8
// k-in-tile = (lane&3)*4 + ((j&2)?16:0) + c   (c = byte 0..3)
__global__ void prep_wA(const float* __restrict__ bw) {
    int idx = blockIdx.x * blockDim.x + threadIdx.x;
    if (idx >= CMID * KCONV / 4) return;
    int j    = idx & 3;
    int lane = (idx >> 2) & 31;
    int sub  = (idx >> 7) & 7;
    int t10  = idx >> 10;
    int kt   = t10 % KT1;
    int mb   = t10 / KT1;
    int m    = mb * 128 + sub * 16 + (lane >> 2) + ((j & 1) << 3);
    int kb   = ((lane & 3) << 2) + ((j & 2) ? 16 : 0);
    int r    = kt >> 3;
    int kh   = r / 3, kw = r % 3;
    int ci0  = (kt & 7) * 32;
    uint32_t w = 0;
    #pragma unroll
    for (int c = 0; c < 4; ++c) {
        int ci = ci0 + kb + c;
        float v = bw[((m * CIN + ci) * 3 + kh) * 3 + kw];   // -1 / 0 / +1
        w |= ((uint32_t)(uint8_t)(signed char)(int)v) << (8 * c);
    }
    g_wA[idx] = w;
}

// 1x1 weights transposed to [k][m], tf32-rounded
__global__ void prep_wB(const float* __restrict__ fw) {
    int idx = blockIdx.x * blockDim.x + threadIdx.x;
    if (idx >= CMID * COUT) return;
    int m = idx % COUT;
    int k = idx / COUT;
    g_wB[idx] = __uint_as_float(f2tf32(fw[m * CMID + k]));
}

// x -> 16-bit fixed point q = round(x*4096), split q = 256*qh + ql (both s8)
__global__ void prep_xq(const float* __restrict__ x) {
    int idx = blockIdx.x * blockDim.x + threadIdx.x;
    if (idx >= BATCH * CIN * HW) return;
    int q = __float2int_rn(x[idx] * 4096.0f);
    q = max(-30000, min(30000, q));
    int qh = (q + 128) >> 8;
    int ql = q - (qh << 8);
    g_xh[idx] = (signed char)qh;
    g_xl[idx] = (signed char)ql;
}

// ---------------- conv1: s8 IMMA, block 128x64, 8 warps (4m x 2n), warp 32x32 ----------------
// Stage layout (8192 B): A frag-ordered [0,4096) = 8 subtiles * 512B
//   Bh [4096,6144): region0 (k0-15) [0,1024) + region1 (k16-31) [1024,2048), 16B/pixel
//   Bl [6144,8192): same
#define IMMA(c, a, b0, b1)                                                     \
    asm volatile("mma.sync.aligned.m16n8k32.row.col.s32.s8.s8.s32 "            \
        "{%0,%1,%2,%3}, {%4,%5,%6,%7}, {%8,%9}, {%0,%1,%2,%3};\n"              \
        : "+r"((c)[0]), "+r"((c)[1]), "+r"((c)[2]), "+r"((c)[3])               \
        : "r"((a).x), "r"((a).y), "r"((a).z), "r"((a).w), "r"(b0), "r"(b1))

__global__ __launch_bounds__(256, 2) void conv1_imma()
{
    __shared__ __align__(16) unsigned char sm[2 * 8192];
    const int tid  = threadIdx.x;
    const int lane = tid & 31;
    const int warp = tid >> 5;
    const int b    = blockIdx.z;
    const int mb   = blockIdx.y;          // 0..3 (M block of 128)
    const int n0   = blockIdx.x * 64;     // 49 tiles, exact
    const int wn   = (warp >> 2) * 32;    // 2 n-positions
    const int wsub = (warp & 3) * 2;      // A subtile base (4 m-positions)

    const size_t bofs = (size_t)b * CIN * HW;
    const int p = tid & 63;               // pixel within tile
    const int q = tid >> 6;               // k-quarter 0..3
    const int n = n0 + p;
    const int hh = n / IMGW, ww = n % IMGW;

    signed char sh[8], sl[8];
    int accH[2][4][4], accL[2][4][4];
    #pragma unroll
    for (int mt = 0; mt < 2; ++mt)
        #pragma unroll
        for (int nt = 0; nt < 4; ++nt)
            #pragma unroll
            for (int c = 0; c < 4; ++c) { accH[mt][nt][c] = 0; accL[mt][nt][c] = 0; }

    const char* wsrc = (const char*)g_wA + (size_t)(mb * KT1) * 4096;

    auto loadA = [&](int kt, unsigned char* stg) {
        uint32_t dst = (uint32_t)__cvta_generic_to_shared(stg) + tid * 16;
        CP16(dst, wsrc + (size_t)kt * 4096 + tid * 16);
    };
    auto ldgB = [&](int kt) {
        const int r   = kt >> 3;
        const int ci0 = (kt & 7) * 32 + q * 8;
        const int kh  = r / 3, kw = r % 3;
        const int ih  = hh + kh - 1, iw = ww + kw - 1;
        if (((unsigned)ih < (unsigned)IMGW) && ((unsigned)iw < (unsigned)IMGW)) {
            const signed char* ph = g_xh + bofs + (size_t)ci0 * HW + ih * IMGW + iw;
            const signed char* pl = g_xl + bofs + (size_t)ci0 * HW + ih * IMGW + iw;
            #pragma unroll
            for (int j = 0; j < 8; ++j) {
                sh[j] = __ldg(ph + (size_t)j * HW);
                sl[j] = __ldg(pl + (size_t)j * HW);
            }
        } else {
            #pragma unroll
            for (int j = 0; j < 8; ++j) { sh[j] = 0; sl[j] = 0; }
        }
    };
    auto pack4 = [](const signed char* s) {
        return (uint32_t)(uint8_t)s[0] | ((uint32_t)(uint8_t)s[1] << 8) |
               ((uint32_t)(uint8_t)s[2] << 16) | ((uint32_t)(uint8_t)s[3] << 24);
    };
    auto stsB = [&](unsigned char* stg) {
        const int roff = (q >> 1) * 1024 + p * 16 + (q & 1) * 8;
        *(uint2*)(stg + 4096 + roff) = make_uint2(pack4(sh), pack4(sh + 4));
        *(uint2*)(stg + 6144 + roff) = make_uint2(pack4(sl), pack4(sl + 4));
    };
    auto compute = [&](const unsigned char* stg) {
        int4 af[2];
        #pragma unroll
        for (int mt = 0; mt < 2; ++mt)
            af[mt] = ((const int4*)(stg + (wsub + mt) * 512))[lane];
        const int fo = (lane & 3) * 4;
        #pragma unroll
        for (int nt = 0; nt < 4; ++nt) {
            const int c = (wn + nt * 8 + (lane >> 2)) * 16 + fo;
            uint32_t h0 = *(const uint32_t*)(stg + 4096 + c);
            uint32_t h1 = *(const uint32_t*)(stg + 4096 + 1024 + c);
            uint32_t l0 = *(const uint32_t*)(stg + 6144 + c);
            uint32_t l1 = *(const uint32_t*)(stg + 6144 + 1024 + c);
            #pragma unroll
            for (int mt = 0; mt < 2; ++mt) {
                IMMA(accH[mt][nt], af[mt], h0, h1);
                IMMA(accL[mt][nt], af[mt], l0, l1);
            }
        }
    };

    // ---- pipelined main loop (2-stage) ----
    int buf = 0;
    loadA(0, sm);
    ldgB(0);
    CP_COMMIT();
    for (int kt = 0; kt < KT1; ++kt) {
        unsigned char* stg = sm + buf * 8192;
        CP_WAIT0();
        stsB(stg);
        __syncthreads();
        if (kt + 1 < KT1) {
            loadA(kt + 1, sm + (buf ^ 1) * 8192);
            ldgB(kt + 1);
            CP_COMMIT();
        }
        compute(stg);
        buf ^= 1;
    }

    // ---- epilogue: y = (256*H + L)/4096, relu, round to tf32 ----
    float* dst = g_y + (size_t)b * CMID * HW;
    const float S = 1.0f / 4096.0f;
    #pragma unroll
    for (int mt = 0; mt < 2; ++mt) {
        #pragma unroll
        for (int nt = 0; nt < 4; ++nt) {
            const int r0 = mb * 128 + (warp & 3) * 32 + mt * 16 + (lane >> 2);
            const int cc = n0 + wn + nt * 8 + (lane & 3) * 2;
            int t0 = (accH[mt][nt][0] << 8) + accL[mt][nt][0];
            int t1 = (accH[mt][nt][1] << 8) + accL[mt][nt][1];
            int t2 = (accH[mt][nt][2] << 8) + accL[mt][nt][2];
            int t3 = (accH[mt][nt][3] << 8) + accL[mt][nt][3];
            float2 v0, v1;
            v0.x = __uint_as_float(f2tf32(fmaxf((float)t0 * S, 0.f)));
            v0.y = __uint_as_float(f2tf32(fmaxf((float)t1 * S, 0.f)));
            v1.x = __uint_as_float(f2tf32(fmaxf((float)t2 * S, 0.f)));
            v1.y = __uint_as_float(f2tf32(fmaxf((float)t3 * S, 0.f)));
            *(float2*)&dst[(size_t)r0 * HW + cc]       = v0;
            *(float2*)&dst[(size_t)(r0 + 8) * HW + cc] = v1;
        }
    }
}

// ---------------- conv2: tf32 mma, block 128x64, 8 warps (4m x 2n), warp 32x32 ----------------
// Smem per stage: As[32][136] floats + Bs[32][72] floats, double-buffered (dynamic).
#define MMAT(c, a0, a1, a2, a3, b0, b1)                                        \
    asm volatile("mma.sync.aligned.m16n8k8.row.col.f32.tf32.tf32.f32 "         \
        "{%0,%1,%2,%3}, {%4,%5,%6,%7}, {%8,%9}, {%0,%1,%2,%3};\n"              \
        : "+f"((c)[0]), "+f"((c)[1]), "+f"((c)[2]), "+f"((c)[3])               \
        : "r"(__float_as_uint(a0)), "r"(__float_as_uint(a1)),                  \
          "r"(__float_as_uint(a2)), "r"(__float_as_uint(a3)),                  \
          "r"(__float_as_uint(b0)), "r"(__float_as_uint(b1)))

#define STG2F (32 * 136 + 32 * 72)   // 6656 floats per stage

__global__ __launch_bounds__(256) void conv2_tf32(const float* __restrict__ bias,
                                                  float* __restrict__ outp)
{
    extern __shared__ float sm2[];
    const int tid  = threadIdx.x;
    const int lane = tid & 31;
    const int warp = tid >> 5;
    const int b    = blockIdx.z;
    const int m0   = blockIdx.y * 128;
    const int n0   = blockIdx.x * 64;     // 49 tiles, exact
    const int wm   = (warp & 3) * 32;
    const int wn   = (warp >> 2) * 32;

    const float* Bbase = g_y + (size_t)b * CMID * HW;
    const int arow = tid >> 3, ac = tid & 7;

    float acc[2][4][4];
    #pragma unroll
    for (int i = 0; i < 2; i++)
        #pragma unroll
        for (int j = 0; j < 4; j++)
            #pragma unroll
            for (int c = 0; c < 4; c++) acc[i][j][c] = 0.f;

    auto load = [&](int kt, float* stg) {
        float* As = stg;
        float* Bs = stg + 32 * 136;
        uint32_t ad = (uint32_t)__cvta_generic_to_shared(As);
        uint32_t bd = (uint32_t)__cvta_generic_to_shared(Bs);
        #pragma unroll
        for (int i = 0; i < 4; ++i) {
            int ch = ac + 8 * i;
            CP16(ad + (uint32_t)(arow * 136 + ch * 4) * 4,
                 g_wB + (size_t)(kt * 32 + arow) * COUT + m0 + ch * 4);
        }
        #pragma unroll
        for (int i = 0; i < 2; ++i) {
            int ch = ac + 8 * i;
            CP16(bd + (uint32_t)(arow * 72 + ch * 4) * 4,
                 Bbase + (size_t)(kt * 32 + arow) * HW + n0 + ch * 4);
        }
    };
    auto compute = [&](const float* stg) {
        const float* As = stg;
        const float* Bs = stg + 32 * 136;
        const int gr = lane >> 2;
        #pragma unroll
        for (int kk = 0; kk < 4; ++kk) {
            const int kc = kk * 8 + (lane & 3);
            float a[2][4], bf[4][2];
            #pragma unroll
            for (int mt = 0; mt < 2; ++mt) {
                const int row = wm + mt * 16 + gr;
                a[mt][0] = As[kc * 136 + row];
                a[mt][1] = As[kc * 136 + row + 8];
                a[mt][2] = As[(kc + 4) * 136 + row];
                a[mt][3] = As[(kc + 4) * 136 + row + 8];
            }
            #pragma unroll
            for (int nt = 0; nt < 4; ++nt) {
                const int col = wn + nt * 8 + gr;
                bf[nt][0] = Bs[kc * 72 + col];
                bf[nt][1] = Bs[(kc + 4) * 72 + col];
            }
            #pragma unroll
            for (int mt = 0; mt < 2; ++mt)
                #pragma unroll
                for (int nt = 0; nt < 4; ++nt)
                    MMAT(acc[mt][nt], a[mt][0], a[mt][1], a[mt][2], a[mt][3],
                         bf[nt][0], bf[nt][1]);
        }
    };

    int buf = 0;
    load(0, sm2);
    CP_COMMIT();
    for (int kt = 0; kt < 16; ++kt) {
        float* stg = sm2 + buf * STG2F;
        CP_WAIT0();
        __syncthreads();
        if (kt + 1 < 16) {
            load(kt + 1, sm2 + (buf ^ 1) * STG2F);
            CP_COMMIT();
        }
        compute(stg);
        buf ^= 1;
    }

    float* dst = outp + (size_t)b * COUT * HW;
    const int gr = lane >> 2, gc = (lane & 3) * 2;
    #pragma unroll
    for (int mt = 0; mt < 2; ++mt) {
        #pragma unroll
        for (int nt = 0; nt < 4; ++nt) {
            const int row = m0 + wm + mt * 16 + gr;
            const int col = n0 + wn + nt * 8 + gc;
            const float b0 = bias[row], b1 = bias[row + 8];
            float2 v0 = { acc[mt][nt][0] + b0, acc[mt][nt][1] + b0 };
            float2 v1 = { acc[mt][nt][2] + b1, acc[mt][nt][3] + b1 };
            *(float2*)&dst[(size_t)row * HW + col]       = v0;
            *(float2*)&dst[(size_t)(row + 8) * HW + col] = v1;
        }
    }
}

extern "C" void kernel_launch(void* const* d_in, const int* in_sizes, int n_in,
                              void* d_out, int out_size) {
    (void)in_sizes; (void)n_in; (void)out_size;
    const float* x  = (const float*)d_in[0];
    const float* bw = (const float*)d_in[1];   // binary_w [512,256,3,3]
    const float* fw = (const float*)d_in[2];   // fc_w [256,512,1,1]
    const float* fb = (const float*)d_in[3];   // fc_b [256]
    float* out = (float*)d_out;

    const int smem2 = 2 * STG2F * 4;   // 53248
    cudaFuncSetAttribute(conv2_tf32,
                         cudaFuncAttributeMaxDynamicSharedMemorySize, smem2);

    prep_wA<<<(CMID * KCONV / 4 + 255) / 256, 256>>>(bw);
    prep_wB<<<(CMID * COUT + 255) / 256, 256>>>(fw);
    prep_xq<<<(BATCH * CIN * HW + 255) / 256, 256>>>(x);

    // conv1: M=512 (4 blocks of 128), N=3136 (49 tiles of 64), 32 batches
    conv1_imma<<<dim3(49, 4, 32), 256>>>();
    // conv2: M=256 (2 blocks of 128), N 49 tiles, bias
    conv2_tf32<<<dim3(49, 2, 32), 256, smem2>>>(fb, out);
}

// round 8
// speedup vs baseline: 4.8201x; 4.8201x over previous
#include <cuda_runtime.h>
#include <cuda_fp16.h>
#include <cstdint>

#define CIN   256
#define CMID  512
#define COUT  256
#define IMGW  56
#define HW    3136
#define BATCH 32
#define KCONV 2304

// ---------------- scratch (device globals — allocation-free rule) ----------------
__device__ __align__(16) __half g_xT  [(size_t)BATCH * HW * CIN];    // x transposed [b][px][ci]
__device__ __align__(16) __half g_y16 [(size_t)BATCH * CMID * HW];   // y [b][cm][px]
__device__ __align__(16) __half g_wA16[CMID * KCONV];                // [m][k], k = r*256+ci
__device__ __align__(16) __half g_wB16[COUT * CMID];                 // [cout][cm]

// ---------------- asm helpers ----------------
#define CP16Z(dst, src, sz) \
    asm volatile("cp.async.cg.shared.global [%0], [%1], 16, %2;\n" \
                 :: "r"(dst), "l"(src), "r"(sz))
#define CP_COMMIT()  asm volatile("cp.async.commit_group;\n")
#define CP_WAIT0()   asm volatile("cp.async.wait_group 0;\n")

#define LDSM4(R0,R1,R2,R3,A) \
    asm volatile("ldmatrix.sync.aligned.m8n8.x4.shared.b16 {%0,%1,%2,%3}, [%4];" \
                 : "=r"(R0), "=r"(R1), "=r"(R2), "=r"(R3) : "r"(A))
#define LDSM4T(R0,R1,R2,R3,A) \
    asm volatile("ldmatrix.sync.aligned.m8n8.x4.trans.shared.b16 {%0,%1,%2,%3}, [%4];" \
                 : "=r"(R0), "=r"(R1), "=r"(R2), "=r"(R3) : "r"(A))

#define HMMA(C, A0,A1,A2,A3, B0,B1) \
    asm volatile("mma.sync.aligned.m16n8k16.row.col.f32.f16.f16.f32 " \
        "{%0,%1,%2,%3}, {%4,%5,%6,%7}, {%8,%9}, {%0,%1,%2,%3};\n" \
        : "+f"((C)[0]), "+f"((C)[1]), "+f"((C)[2]), "+f"((C)[3]) \
        : "r"(A0), "r"(A1), "r"(A2), "r"(A3), "r"(B0), "r"(B1))

// ---------------- prep kernels ----------------
// x [b][ci][h][w] -> g_xT [b][px][ci]  (tiled 64x64 transpose via smem)
__global__ void prep_xT(const float* __restrict__ x) {
    __shared__ __half st[64][72];
    const int t   = threadIdx.x;
    const int px0 = blockIdx.x * 64;
    const int ci0 = blockIdx.y * 64;
    const int b   = blockIdx.z;
    #pragma unroll
    for (int i = 0; i < 16; ++i) {
        int id = i * 256 + t;
        int ci = id >> 6, px = id & 63;
        st[px][ci] = __float2half(
            x[((size_t)b * CIN + ci0 + ci) * HW + px0 + px]);
    }
    __syncthreads();
    #pragma unroll
    for (int i = 0; i < 8; ++i) {
        int id = i * 256 + t;
        int px = id >> 5, cc = id & 31;
        __half2 v = *(__half2*)&st[px][cc * 2];
        *(__half2*)&g_xT[((size_t)b * HW + px0 + px) * CIN + ci0 + cc * 2] = v;
    }
}

__global__ void prep_wA16(const float* __restrict__ bw) {
    int idx = blockIdx.x * blockDim.x + threadIdx.x;
    if (idx >= CMID * KCONV) return;
    int k = idx % KCONV, m = idx / KCONV;
    int ci = k & 255, r = k >> 8;
    int kh = r / 3, kw = r % 3;
    g_wA16[idx] = __float2half(bw[((m * CIN + ci) * 3 + kh) * 3 + kw]);  // ternary exact
}
__global__ void prep_wB16(const float* __restrict__ fw) {
    int idx = blockIdx.x * blockDim.x + threadIdx.x;
    if (idx >= COUT * CMID) return;
    g_wB16[idx] = __float2half(fw[idx]);
}

// ---------------- fp16 HMMA GEMM ----------------
// Block 128x128, BK=64, 8 warps (2m x 4n), warp tile 64x32.
// Smem per stage 32KB: A [128m][64k] (swizzled 128B rows) + B tile 16KB.
//   conv1 B: [128 n(px)][64 k(ci)]  (non-trans ldmatrix)
//   conv2 B: [64 k(cm)][128 n(px)]  (trans ldmatrix)
#define STAGEB 32768

template <bool CONV1>
__global__ __launch_bounds__(256, 2)
void conv_hmma(const float* __restrict__ bias, float* __restrict__ outp)
{
    constexpr int Ktot = CONV1 ? KCONV : CMID;
    constexpr int KT   = Ktot / 64;

    extern __shared__ char smem[];
    const uint32_t sb = (uint32_t)__cvta_generic_to_shared(smem);
    const int t    = threadIdx.x;
    const int lane = t & 31;
    const int warp = t >> 5;
    const int b    = blockIdx.z;
    const int mb   = blockIdx.y;
    const int n0   = blockIdx.x * 128;
    const int wm   = (warp & 1) * 64;
    const int wn   = (warp >> 1) * 32;

    const __half* Asrc = (CONV1 ? g_wA16 : g_wB16) + (size_t)(mb * 128) * Ktot;

    // conv1 B pixel coords: thread covers px_i = i*32 + (t>>3), chunk c = t&7
    const int bc  = t & 7;
    int oh[4], ow[4], ov[4];
    #pragma unroll
    for (int i = 0; i < 4; ++i) {
        int px = i * 32 + (t >> 3);
        int opx = n0 + px;
        ov[i] = opx < HW;
        oh[i] = (opx < HW ? opx : 0) / IMGW;
        ow[i] = (opx < HW ? opx : 0) % IMGW;
    }

    float acc[4][4][4];
    #pragma unroll
    for (int i = 0; i < 4; i++)
        #pragma unroll
        for (int j = 0; j < 4; j++)
            #pragma unroll
            for (int c = 0; c < 4; c++) acc[i][j][c] = 0.f;

    auto load = [&](int kt, int s) {
        const uint32_t st = sb + s * STAGEB;
        // A: 128 rows x 128B
        {
            const int r0 = t >> 3, c = t & 7;
            #pragma unroll
            for (int i = 0; i < 4; ++i) {
                int row = r0 + 32 * i;
                CP16Z(st + row * 128 + ((c ^ (row & 7)) << 4),
                      Asrc + (size_t)row * Ktot + kt * 64 + c * 8, 16u);
            }
        }
        const uint32_t bst = st + 16384;
        if (CONV1) {
            const int r   = kt >> 2;            // 0..8
            const int kh  = r / 3, kw = r % 3;
            const int ci0 = (kt & 3) * 64;
            #pragma unroll
            for (int i = 0; i < 4; ++i) {
                int px = i * 32 + (t >> 3);
                int ih = oh[i] + kh - 1, iw = ow[i] + kw - 1;
                bool val = ov[i] && ((unsigned)ih < (unsigned)IMGW) &&
                           ((unsigned)iw < (unsigned)IMGW);
                const __half* src = g_xT +
                    ((size_t)b * HW + (val ? ih * IMGW + iw : 0)) * CIN + ci0 + bc * 8;
                CP16Z(bst + px * 128 + ((bc ^ (px & 7)) << 4), src, val ? 16u : 0u);
            }
        } else {
            const int c = t & 15;
            const bool val = (n0 + c * 8) < HW;
            #pragma unroll
            for (int i = 0; i < 4; ++i) {
                int row = i * 16 + (t >> 4);
                const __half* src = g_y16 +
                    ((size_t)b * CMID + kt * 64 + row) * HW + n0 + c * 8;
                CP16Z(bst + row * 256 + ((c ^ (row & 7)) << 4), src, val ? 16u : 0u);
            }
        }
    };

    auto compute = [&](int s) {
        const uint32_t sa  = sb + s * STAGEB;
        const uint32_t sbt = sa + 16384;
        #pragma unroll
        for (int ks = 0; ks < 4; ++ks) {
            uint32_t a[4][4];
            #pragma unroll
            for (int mt = 0; mt < 4; ++mt) {
                int row = wm + mt * 16 + ((lane >> 3) & 1) * 8 + (lane & 7);
                int ch  = ks * 2 + (lane >> 4);
                LDSM4(a[mt][0], a[mt][1], a[mt][2], a[mt][3],
                      sa + row * 128 + ((ch ^ (row & 7)) << 4));
            }
            uint32_t bf[4][2];
            #pragma unroll
            for (int p = 0; p < 2; ++p) {
                uint32_t r0, r1, r2, r3;
                if (CONV1) {
                    int row = wn + p * 16 + ((lane >> 3) & 1) * 8 + (lane & 7);
                    int ch  = ks * 2 + (lane >> 4);
                    LDSM4(r0, r1, r2, r3,
                          sbt + row * 128 + ((ch ^ (row & 7)) << 4));
                    bf[p*2+0][0] = r0; bf[p*2+0][1] = r2;   // n8 @ +0
                    bf[p*2+1][0] = r1; bf[p*2+1][1] = r3;   // n8 @ +8
                } else {
                    int krow = ks * 16 + ((lane >> 3) & 1) * 8 + (lane & 7);
                    int nch  = (wn >> 3) + p * 2 + (lane >> 4);
                    LDSM4T(r0, r1, r2, r3,
                           sbt + krow * 256 + ((nch ^ (krow & 7)) << 4));
                    bf[p*2+0][0] = r0; bf[p*2+0][1] = r1;   // n8 @ +0
                    bf[p*2+1][0] = r2; bf[p*2+1][1] = r3;   // n8 @ +8
                }
            }
            #pragma unroll
            for (int mt = 0; mt < 4; ++mt)
                #pragma unroll
                for (int nt = 0; nt < 4; ++nt)
                    HMMA(acc[mt][nt], a[mt][0], a[mt][1], a[mt][2], a[mt][3],
                         bf[nt][0], bf[nt][1]);
        }
    };

    // ---- 2-stage pipeline ----
    load(0, 0);
    CP_COMMIT();
    for (int kt = 0; kt < KT; ++kt) {
        CP_WAIT0();
        __syncthreads();
        if (kt + 1 < KT) {
            load(kt + 1, (kt + 1) & 1);
            CP_COMMIT();
        }
        compute(kt & 1);
    }

    // ---- epilogue ----
    const int g  = lane >> 2;
    const int tt = lane & 3;
    if (CONV1) {
        __half* dst = g_y16 + (size_t)b * CMID * HW;
        #pragma unroll
        for (int mt = 0; mt < 4; ++mt) {
            #pragma unroll
            for (int nt = 0; nt < 4; ++nt) {
                const int m   = mb * 128 + wm + mt * 16 + g;
                const int col = n0 + wn + nt * 8 + tt * 2;
                if (col < HW) {
                    __half2 v0 = __floats2half2_rn(fmaxf(acc[mt][nt][0], 0.f),
                                                   fmaxf(acc[mt][nt][1], 0.f));
                    __half2 v1 = __floats2half2_rn(fmaxf(acc[mt][nt][2], 0.f),
                                                   fmaxf(acc[mt][nt][3], 0.f));
                    *(__half2*)&dst[(size_t)m * HW + col]       = v0;
                    *(__half2*)&dst[(size_t)(m + 8) * HW + col] = v1;
                }
            }
        }
    } else {
        float* dst = outp + (size_t)b * COUT * HW;
        #pragma unroll
        for (int mt = 0; mt < 4; ++mt) {
            #pragma unroll
            for (int nt = 0; nt < 4; ++nt) {
                const int m   = mb * 128 + wm + mt * 16 + g;
                const int col = n0 + wn + nt * 8 + tt * 2;
                if (col < HW) {
                    const float b0 = bias[m], b1 = bias[m + 8];
                    float2 v0 = { acc[mt][nt][0] + b0, acc[mt][nt][1] + b0 };
                    float2 v1 = { acc[mt][nt][2] + b1, acc[mt][nt][3] + b1 };
                    *(float2*)&dst[(size_t)m * HW + col]       = v0;
                    *(float2*)&dst[(size_t)(m + 8) * HW + col] = v1;
                }
            }
        }
    }
}

extern "C" void kernel_launch(void* const* d_in, const int* in_sizes, int n_in,
                              void* d_out, int out_size) {
    (void)in_sizes; (void)n_in; (void)out_size;
    const float* x  = (const float*)d_in[0];
    const float* bw = (const float*)d_in[1];   // binary_w [512,256,3,3]
    const float* fw = (const float*)d_in[2];   // fc_w [256,512,1,1]
    const float* fb = (const float*)d_in[3];   // fc_b [256]
    float* out = (float*)d_out;

    const int smem_bytes = 2 * STAGEB;   // 65536
    cudaFuncSetAttribute(conv_hmma<true>,
                         cudaFuncAttributeMaxDynamicSharedMemorySize, smem_bytes);
    cudaFuncSetAttribute(conv_hmma<false>,
                         cudaFuncAttributeMaxDynamicSharedMemorySize, smem_bytes);

    prep_xT  <<<dim3(49, 4, 32), 256>>>(x);
    prep_wA16<<<(CMID * KCONV + 255) / 256, 256>>>(bw);
    prep_wB16<<<(COUT * CMID + 255) / 256, 256>>>(fw);

    // conv1 + relu -> g_y16 : M=512 (4 blocks), N=3136 (25 tiles of 128)
    conv_hmma<true ><<<dim3(25, 4, 32), 256, smem_bytes>>>(nullptr, nullptr);
    // conv2 + bias -> out : M=256 (2 blocks)
    conv_hmma<false><<<dim3(25, 2, 32), 256, smem_bytes>>>(fb, out);
}